// round 1
// baseline (speedup 1.0000x reference)
#include <cuda_runtime.h>
#include <cstdint>

#define Bc 64
#define Nc 512
#define Dc 256
#define Ec 128
#define NITER 20
#define NROWS (Bc*Nc)          // 32768
#define NCHUNK 8               // i-chunks for column reductions

// ---------------- scratch (static device arrays; no allocation) ----------------
__device__ float g_a[Bc*Nc*Ec];          // (x_out @ W_a) * w_aff   [B,N,E]
__device__ float g_b[Bc*Nc*Ec];          // x_in @ W_b              [B,N,E]
__device__ float g_aff[Bc*Nc*Nc];        // affinity                [B,N,N]
__device__ float g_K[Bc*Nc*Nc];          // Sinkhorn kernel matrix  [B,N,N]
__device__ float g_r1[NROWS];            // 0.5 / colsum(exp(aff))  per (b,j)
__device__ float g_r2[NROWS];            // 0.5 / rowsum(exp(aff))  per (b,i)
__device__ float g_u[NROWS];             // row scaling u
__device__ float g_vpart[NCHUNK*NROWS];  // partial column sums (also reused as exp-colsum partials)
__device__ int   g_mask_mode;            // 0=int32, 1=float32, 2=uint8

// ---------------- mask dtype detection ----------------
__global__ void detect_mask_kernel(const unsigned int* __restrict__ m) {
    __shared__ int bad_i32, bad_f32;
    if (threadIdx.x == 0) { bad_i32 = 0; bad_f32 = 0; }
    __syncthreads();
    // 8192 words == 32768 bytes: exactly the buffer if uint8, a prefix otherwise.
    for (int i = threadIdx.x; i < 8192; i += blockDim.x) {
        unsigned int w = m[i];
        if (w != 0u && w != 1u)          atomicOr(&bad_i32, 1);
        if (w != 0u && w != 0x3F800000u) atomicOr(&bad_f32, 1);
    }
    __syncthreads();
    if (threadIdx.x == 0) g_mask_mode = bad_i32 ? (bad_f32 ? 2 : 1) : 0;
}

__device__ __forceinline__ bool read_mask(const void* mp, int row) {
    int mode = g_mask_mode;
    if (mode == 2) return ((const unsigned char*)mp)[row] != 0;
    if (mode == 1) return ((const float*)mp)[row] != 0.0f;
    return ((const int*)mp)[row] != 0;
}

// ---------------- prep GEMM: g_a / g_b = X @ W (M=32768, N=128, K=256) ----------------
// 128x128 block tile, 8x8 per-thread tile, 256 threads, BK=16. gridDim.z selects a vs b.
#define PBK 16
#define ASTRIDE 132   // keeps float4 (16B) alignment for As[k][m] accesses

__global__ __launch_bounds__(256) void prep_gemm_kernel(
    const float* __restrict__ in_emb, const void* __restrict__ maskp,
    const float* __restrict__ out_emb, const float* __restrict__ pad,
    const float* __restrict__ pos, const float* __restrict__ Wa,
    const float* __restrict__ Wb, const float* __restrict__ w_aff)
{
    __shared__ float As[PBK][ASTRIDE];
    __shared__ float Bs[PBK][128];
    const int zb = blockIdx.z;
    const int row0 = blockIdx.x * 128;
    const int tid = threadIdx.x;
    const float* W = zb ? Wb : Wa;
    float acc[8][8] = {};
    const int tm0 = (tid / 16) * 8;
    const int tn0 = (tid % 16) * 8;
    const int lm = tid >> 2, kg = tid & 3;

    for (int k0 = 0; k0 < Dc; k0 += PBK) {
        #pragma unroll
        for (int p = 0; p < 2; p++) {
            int m = lm + p * 64;
            int row = row0 + m;
            int n = row & (Nc - 1);
            int kk = k0 + kg * 4;
            float4 v;
            if (zb == 0) {
                float4 a4 = *(const float4*)&out_emb[(size_t)row * Dc + kk];
                float4 p4 = *(const float4*)&pos[n * Dc + kk];
                v = make_float4(a4.x + p4.x, a4.y + p4.y, a4.z + p4.z, a4.w + p4.w);
            } else {
                if (read_mask(maskp, row)) v = *(const float4*)&pad[kk];
                else                       v = *(const float4*)&in_emb[(size_t)row * Dc + kk];
            }
            As[kg*4+0][m] = v.x; As[kg*4+1][m] = v.y;
            As[kg*4+2][m] = v.z; As[kg*4+3][m] = v.w;
        }
        {
            int r = tid >> 5;           // 0..7
            int c4 = (tid & 31) * 4;
            #pragma unroll
            for (int p = 0; p < 2; p++) {
                int kk = r + p * 8;
                *(float4*)&Bs[kk][c4] = *(const float4*)&W[(k0 + kk) * Ec + c4];
            }
        }
        __syncthreads();
        #pragma unroll
        for (int k = 0; k < PBK; k++) {
            float ra[8], rb[8];
            *(float4*)&ra[0] = *(float4*)&As[k][tm0];
            *(float4*)&ra[4] = *(float4*)&As[k][tm0 + 4];
            *(float4*)&rb[0] = *(float4*)&Bs[k][tn0];
            *(float4*)&rb[4] = *(float4*)&Bs[k][tn0 + 4];
            #pragma unroll
            for (int mi = 0; mi < 8; mi++)
                #pragma unroll
                for (int ni = 0; ni < 8; ni++)
                    acc[mi][ni] += ra[mi] * rb[ni];
        }
        __syncthreads();
    }

    float* dst = zb ? g_b : g_a;
    float wv[8];
    if (zb == 0) {
        *(float4*)&wv[0] = *(const float4*)&w_aff[tn0];
        *(float4*)&wv[4] = *(const float4*)&w_aff[tn0 + 4];
    } else {
        #pragma unroll
        for (int i = 0; i < 8; i++) wv[i] = 1.0f;
    }
    #pragma unroll
    for (int mi = 0; mi < 8; mi++) {
        int row = row0 + tm0 + mi;
        float4 o0 = make_float4(acc[mi][0]*wv[0], acc[mi][1]*wv[1], acc[mi][2]*wv[2], acc[mi][3]*wv[3]);
        float4 o1 = make_float4(acc[mi][4]*wv[4], acc[mi][5]*wv[5], acc[mi][6]*wv[6], acc[mi][7]*wv[7]);
        *(float4*)&dst[(size_t)row * Ec + tn0]     = o0;
        *(float4*)&dst[(size_t)row * Ec + tn0 + 4] = o1;
    }
}

// ---------------- batched affinity GEMM: aff[b] = a[b] @ b[b]^T + b_aff ----------------
__global__ __launch_bounds__(256) void aff_gemm_kernel(const float* __restrict__ baff)
{
    __shared__ float As[PBK][ASTRIDE];
    __shared__ float Bs[PBK][ASTRIDE];
    const int b = blockIdx.z;
    const int i0 = blockIdx.x * 128, j0 = blockIdx.y * 128;
    const int tid = threadIdx.x;
    float acc[8][8] = {};
    const int tm0 = (tid / 16) * 8, tn0 = (tid % 16) * 8;
    const int lm = tid >> 2, kg = tid & 3;
    const float* Ab = g_a + (size_t)b * Nc * Ec;
    const float* Bb = g_b + (size_t)b * Nc * Ec;

    for (int k0 = 0; k0 < Ec; k0 += PBK) {
        #pragma unroll
        for (int p = 0; p < 2; p++) {
            int m = lm + p * 64;
            float4 va = *(const float4*)&Ab[(size_t)(i0 + m) * Ec + k0 + kg * 4];
            As[kg*4+0][m] = va.x; As[kg*4+1][m] = va.y;
            As[kg*4+2][m] = va.z; As[kg*4+3][m] = va.w;
            float4 vb = *(const float4*)&Bb[(size_t)(j0 + m) * Ec + k0 + kg * 4];
            Bs[kg*4+0][m] = vb.x; Bs[kg*4+1][m] = vb.y;
            Bs[kg*4+2][m] = vb.z; Bs[kg*4+3][m] = vb.w;
        }
        __syncthreads();
        #pragma unroll
        for (int k = 0; k < PBK; k++) {
            float ra[8], rb[8];
            *(float4*)&ra[0] = *(float4*)&As[k][tm0];
            *(float4*)&ra[4] = *(float4*)&As[k][tm0 + 4];
            *(float4*)&rb[0] = *(float4*)&Bs[k][tn0];
            *(float4*)&rb[4] = *(float4*)&Bs[k][tn0 + 4];
            #pragma unroll
            for (int mi = 0; mi < 8; mi++)
                #pragma unroll
                for (int ni = 0; ni < 8; ni++)
                    acc[mi][ni] += ra[mi] * rb[ni];
        }
        __syncthreads();
    }

    const float bv = baff[0];
    float* dst = g_aff + (size_t)b * Nc * Nc;
    #pragma unroll
    for (int mi = 0; mi < 8; mi++) {
        int i = i0 + tm0 + mi;
        float4 o0 = make_float4(acc[mi][0]+bv, acc[mi][1]+bv, acc[mi][2]+bv, acc[mi][3]+bv);
        float4 o1 = make_float4(acc[mi][4]+bv, acc[mi][5]+bv, acc[mi][6]+bv, acc[mi][7]+bv);
        *(float4*)&dst[(size_t)i * Nc + j0 + tn0]     = o0;
        *(float4*)&dst[(size_t)i * Nc + j0 + tn0 + 4] = o1;
    }
}

// ---------------- row sum of exp(aff): r2 = 0.5 / rowsum ----------------
__global__ __launch_bounds__(256) void rowsum_kernel() {
    int warp = threadIdx.x >> 5, lane = threadIdx.x & 31;
    int row = blockIdx.x * 8 + warp;
    const float* p = g_aff + (size_t)row * Nc;
    float acc = 0.f;
    #pragma unroll
    for (int it = 0; it < 4; it++) {
        float4 v = *(const float4*)&p[it * 128 + lane * 4];
        acc += __expf(v.x) + __expf(v.y) + __expf(v.z) + __expf(v.w);
    }
    #pragma unroll
    for (int o = 16; o; o >>= 1) acc += __shfl_xor_sync(0xffffffffu, acc, o);
    if (lane == 0) g_r2[row] = 0.5f / acc;
}

// ---------------- column sum of exp(aff), partials over 8 i-chunks ----------------
__global__ __launch_bounds__(512) void colsum_kernel() {
    int chunk = blockIdx.x, b = blockIdx.y, j = threadIdx.x;
    const float* p = g_aff + ((size_t)b * Nc + chunk * 64) * Nc + j;
    float acc = 0.f;
    #pragma unroll 8
    for (int ii = 0; ii < 64; ii++) acc += __expf(p[(size_t)ii * Nc]);
    g_vpart[((size_t)chunk * Bc + b) * Nc + j] = acc;   // reused as colsum partials here
}

__global__ __launch_bounds__(256) void colfin_kernel() {
    int idx = blockIdx.x * 256 + threadIdx.x;   // < NROWS
    float s = 0.f;
    #pragma unroll
    for (int c = 0; c < NCHUNK; c++) s += g_vpart[(size_t)c * NROWS + idx];
    g_r1[idx] = 0.5f / s;
}

// ---------------- K = exp(aff) * (r1[b,j] + r2[b,i]) ----------------
__global__ __launch_bounds__(256) void kbuild_kernel() {
    int idx4 = blockIdx.x * 256 + threadIdx.x;   // float4 index, total B*N*N/4
    int j4 = idx4 & 127;
    int rowIdx = idx4 >> 7;
    int b = rowIdx >> 9;
    float4 a4 = ((const float4*)g_aff)[idx4];
    float r2v = g_r2[rowIdx];
    float4 r1v = *(const float4*)&g_r1[b * Nc + j4 * 4];
    float4 o;
    o.x = __expf(a4.x) * (r1v.x + r2v);
    o.y = __expf(a4.y) * (r1v.y + r2v);
    o.z = __expf(a4.z) * (r1v.z + r2v);
    o.w = __expf(a4.w) * (r1v.w + r2v);
    ((float4*)g_K)[idx4] = o;
}

// ---------------- v-partials init so that first v == 1 ----------------
__global__ __launch_bounds__(256) void vinit_kernel() {
    int idx = blockIdx.x * 256 + threadIdx.x;    // < NCHUNK*NROWS
    g_vpart[idx] = (idx < NROWS) ? 1.0f : 0.0f;
}

// ---------------- Sinkhorn row matvec: u = 1/(K v); v reconstructed from partials ----------------
__global__ __launch_bounds__(512) void rowmv_kernel() {
    __shared__ float v_s[Nc];
    int rb = blockIdx.x, b = blockIdx.y;
    int tid = threadIdx.x;
    {
        float s = 0.f;
        #pragma unroll
        for (int c = 0; c < NCHUNK; c++) s += g_vpart[(size_t)c * NROWS + b * Nc + tid];
        v_s[tid] = 1.0f / s;
    }
    __syncthreads();
    int warp = tid >> 5, lane = tid & 31;
    int i0 = rb * 64 + warp * 4;
    #pragma unroll
    for (int rr = 0; rr < 4; rr++) {
        int i = i0 + rr;
        const float* kp = g_K + ((size_t)b * Nc + i) * Nc;
        float acc = 0.f;
        #pragma unroll
        for (int it = 0; it < 4; it++) {
            float4 kv = *(const float4*)&kp[it * 128 + lane * 4];
            float4 vv = *(const float4*)&v_s[it * 128 + lane * 4];
            acc += kv.x * vv.x + kv.y * vv.y + kv.z * vv.z + kv.w * vv.w;
        }
        #pragma unroll
        for (int o = 16; o; o >>= 1) acc += __shfl_xor_sync(0xffffffffu, acc, o);
        if (lane == 0) g_u[b * Nc + i] = 1.0f / acc;
    }
}

// ---------------- Sinkhorn col matvec partials: vpart[c] = sum_{i in chunk} K^T u ----------------
__global__ __launch_bounds__(512) void colmv_kernel() {
    __shared__ float u_s[64];
    int chunk = blockIdx.x, b = blockIdx.y;
    int j = threadIdx.x;
    if (j < 64) u_s[j] = g_u[b * Nc + chunk * 64 + j];
    __syncthreads();
    const float* kp = g_K + ((size_t)b * Nc + chunk * 64) * Nc + j;
    float acc = 0.f;
    #pragma unroll 8
    for (int ii = 0; ii < 64; ii++) acc += kp[(size_t)ii * Nc] * u_s[ii];
    g_vpart[((size_t)chunk * Bc + b) * Nc + j] = acc;
}

// ---------------- final: out = u[i] * K * v[j] ----------------
__global__ __launch_bounds__(512) void final_kernel(float* __restrict__ out) {
    __shared__ float u_s[64];
    int rb = blockIdx.x, b = blockIdx.y;
    int tid = threadIdx.x;
    float s = 0.f;
    #pragma unroll
    for (int c = 0; c < NCHUNK; c++) s += g_vpart[(size_t)c * NROWS + b * Nc + tid];
    float vj = 1.0f / s;
    if (tid < 64) u_s[tid] = g_u[b * Nc + rb * 64 + tid];
    __syncthreads();
    #pragma unroll 4
    for (int ii = 0; ii < 64; ii++) {
        size_t off = ((size_t)b * Nc + rb * 64 + ii) * Nc + tid;
        out[off] = u_s[ii] * g_K[off] * vj;
    }
}

// ---------------- launch ----------------
extern "C" void kernel_launch(void* const* d_in, const int* in_sizes, int n_in,
                              void* d_out, int out_size) {
    const float* in_emb  = (const float*)d_in[0];
    const void*  maskp   = d_in[1];
    const float* out_emb = (const float*)d_in[2];
    const float* pad     = (const float*)d_in[3];
    const float* pos     = (const float*)d_in[4];
    const float* Wa      = (const float*)d_in[5];
    const float* Wb      = (const float*)d_in[6];
    const float* w_aff   = (const float*)d_in[7];
    const float* baff    = (const float*)d_in[8];

    detect_mask_kernel<<<1, 256>>>((const unsigned int*)maskp);
    prep_gemm_kernel<<<dim3(NROWS / 128, 1, 2), 256>>>(in_emb, maskp, out_emb, pad, pos, Wa, Wb, w_aff);
    aff_gemm_kernel<<<dim3(4, 4, Bc), 256>>>(baff);
    rowsum_kernel<<<NROWS / 8, 256>>>();
    colsum_kernel<<<dim3(NCHUNK, Bc), 512>>>();
    colfin_kernel<<<NROWS / 256, 256>>>();
    kbuild_kernel<<<(Bc * Nc * Nc / 4) / 256, 256>>>();
    vinit_kernel<<<(NCHUNK * NROWS) / 256, 256>>>();
    for (int t = 0; t < NITER; t++) {
        rowmv_kernel<<<dim3(8, Bc), 512>>>();
        colmv_kernel<<<dim3(NCHUNK, Bc), 512>>>();
    }
    final_kernel<<<dim3(8, Bc), 512>>>((float*)d_out);
}

// round 3
// speedup vs baseline: 1.5350x; 1.5350x over previous
#include <cuda_runtime.h>
#include <cuda_fp16.h>
#include <cstdint>

#define Bc 64
#define Nc 512
#define Dc 256
#define Ec 128
#define NITER 20
#define NROWS (Bc*Nc)          // 32768
#define NCHUNK 8               // i-chunks for column reductions

// ---------------- scratch (static device arrays; no allocation) ----------------
__device__ float  g_a[Bc*Nc*Ec];          // (x_out @ W_a) * w_aff   [B,N,E]
__device__ float  g_b[Bc*Nc*Ec];          // x_in @ W_b              [B,N,E]
__device__ float  g_aff[Bc*Nc*Nc];        // affinity                [B,N,N]  (67 MB)
__device__ __half g_Kh[Bc*Nc*Nc];         // fp16 Sinkhorn kernel    [B,N,N]  (33.5 MB, L2-resident)
__device__ float  g_r1[NROWS];            // 0.5 / colsum(exp(aff))  per (b,j)
__device__ float  g_r2[NROWS];            // 0.5 / rowsum(exp(aff))  per (b,i)
__device__ float  g_u[NROWS];             // row scaling u
__device__ float  g_vpart[NCHUNK*NROWS];  // partial column sums
__device__ int    g_mask_mode;            // 0=int32, 1=float32, 2=uint8

// ---------------- mask dtype detection ----------------
__global__ void detect_mask_kernel(const unsigned int* __restrict__ m) {
    __shared__ int bad_i32, bad_f32;
    if (threadIdx.x == 0) { bad_i32 = 0; bad_f32 = 0; }
    __syncthreads();
    for (int i = threadIdx.x; i < 8192; i += blockDim.x) {
        unsigned int w = m[i];
        if (w != 0u && w != 1u)          atomicOr(&bad_i32, 1);
        if (w != 0u && w != 0x3F800000u) atomicOr(&bad_f32, 1);
    }
    __syncthreads();
    if (threadIdx.x == 0) g_mask_mode = bad_i32 ? (bad_f32 ? 2 : 1) : 0;
}

__device__ __forceinline__ bool read_mask(const void* mp, int row) {
    int mode = g_mask_mode;
    if (mode == 2) return ((const unsigned char*)mp)[row] != 0;
    if (mode == 1) return ((const float*)mp)[row] != 0.0f;
    return ((const int*)mp)[row] != 0;
}

// ---------------- prep GEMM: g_a / g_b = X @ W (M=32768, N=128, K=256) ----------------
#define PBK 16
#define ASTRIDE 132

__global__ __launch_bounds__(256) void prep_gemm_kernel(
    const float* __restrict__ in_emb, const void* __restrict__ maskp,
    const float* __restrict__ out_emb, const float* __restrict__ pad,
    const float* __restrict__ pos, const float* __restrict__ Wa,
    const float* __restrict__ Wb, const float* __restrict__ w_aff)
{
    __shared__ float As[PBK][ASTRIDE];
    __shared__ float Bs[PBK][128];
    const int zb = blockIdx.z;
    const int row0 = blockIdx.x * 128;
    const int tid = threadIdx.x;
    const float* W = zb ? Wb : Wa;
    float acc[8][8] = {};
    const int tm0 = (tid / 16) * 8;
    const int tn0 = (tid % 16) * 8;
    const int lm = tid >> 2, kg = tid & 3;

    for (int k0 = 0; k0 < Dc; k0 += PBK) {
        #pragma unroll
        for (int p = 0; p < 2; p++) {
            int m = lm + p * 64;
            int row = row0 + m;
            int n = row & (Nc - 1);
            int kk = k0 + kg * 4;
            float4 v;
            if (zb == 0) {
                float4 a4 = *(const float4*)&out_emb[(size_t)row * Dc + kk];
                float4 p4 = *(const float4*)&pos[n * Dc + kk];
                v = make_float4(a4.x + p4.x, a4.y + p4.y, a4.z + p4.z, a4.w + p4.w);
            } else {
                if (read_mask(maskp, row)) v = *(const float4*)&pad[kk];
                else                       v = *(const float4*)&in_emb[(size_t)row * Dc + kk];
            }
            As[kg*4+0][m] = v.x; As[kg*4+1][m] = v.y;
            As[kg*4+2][m] = v.z; As[kg*4+3][m] = v.w;
        }
        {
            int r = tid >> 5;
            int c4 = (tid & 31) * 4;
            #pragma unroll
            for (int p = 0; p < 2; p++) {
                int kk = r + p * 8;
                *(float4*)&Bs[kk][c4] = *(const float4*)&W[(k0 + kk) * Ec + c4];
            }
        }
        __syncthreads();
        #pragma unroll
        for (int k = 0; k < PBK; k++) {
            float ra[8], rb[8];
            *(float4*)&ra[0] = *(float4*)&As[k][tm0];
            *(float4*)&ra[4] = *(float4*)&As[k][tm0 + 4];
            *(float4*)&rb[0] = *(float4*)&Bs[k][tn0];
            *(float4*)&rb[4] = *(float4*)&Bs[k][tn0 + 4];
            #pragma unroll
            for (int mi = 0; mi < 8; mi++)
                #pragma unroll
                for (int ni = 0; ni < 8; ni++)
                    acc[mi][ni] += ra[mi] * rb[ni];
        }
        __syncthreads();
    }

    float* dst = zb ? g_b : g_a;
    float wv[8];
    if (zb == 0) {
        *(float4*)&wv[0] = *(const float4*)&w_aff[tn0];
        *(float4*)&wv[4] = *(const float4*)&w_aff[tn0 + 4];
    } else {
        #pragma unroll
        for (int i = 0; i < 8; i++) wv[i] = 1.0f;
    }
    #pragma unroll
    for (int mi = 0; mi < 8; mi++) {
        int row = row0 + tm0 + mi;
        float4 o0 = make_float4(acc[mi][0]*wv[0], acc[mi][1]*wv[1], acc[mi][2]*wv[2], acc[mi][3]*wv[3]);
        float4 o1 = make_float4(acc[mi][4]*wv[4], acc[mi][5]*wv[5], acc[mi][6]*wv[6], acc[mi][7]*wv[7]);
        *(float4*)&dst[(size_t)row * Ec + tn0]     = o0;
        *(float4*)&dst[(size_t)row * Ec + tn0 + 4] = o1;
    }
}

// ---------------- batched affinity GEMM: aff[b] = a[b] @ b[b]^T + b_aff ----------------
__global__ __launch_bounds__(256) void aff_gemm_kernel(const float* __restrict__ baff)
{
    __shared__ float As[PBK][ASTRIDE];
    __shared__ float Bs[PBK][ASTRIDE];
    const int b = blockIdx.z;
    const int i0 = blockIdx.x * 128, j0 = blockIdx.y * 128;
    const int tid = threadIdx.x;
    float acc[8][8] = {};
    const int tm0 = (tid / 16) * 8, tn0 = (tid % 16) * 8;
    const int lm = tid >> 2, kg = tid & 3;
    const float* Ab = g_a + (size_t)b * Nc * Ec;
    const float* Bb = g_b + (size_t)b * Nc * Ec;

    for (int k0 = 0; k0 < Ec; k0 += PBK) {
        #pragma unroll
        for (int p = 0; p < 2; p++) {
            int m = lm + p * 64;
            float4 va = *(const float4*)&Ab[(size_t)(i0 + m) * Ec + k0 + kg * 4];
            As[kg*4+0][m] = va.x; As[kg*4+1][m] = va.y;
            As[kg*4+2][m] = va.z; As[kg*4+3][m] = va.w;
            float4 vb = *(const float4*)&Bb[(size_t)(j0 + m) * Ec + k0 + kg * 4];
            Bs[kg*4+0][m] = vb.x; Bs[kg*4+1][m] = vb.y;
            Bs[kg*4+2][m] = vb.z; Bs[kg*4+3][m] = vb.w;
        }
        __syncthreads();
        #pragma unroll
        for (int k = 0; k < PBK; k++) {
            float ra[8], rb[8];
            *(float4*)&ra[0] = *(float4*)&As[k][tm0];
            *(float4*)&ra[4] = *(float4*)&As[k][tm0 + 4];
            *(float4*)&rb[0] = *(float4*)&Bs[k][tn0];
            *(float4*)&rb[4] = *(float4*)&Bs[k][tn0 + 4];
            #pragma unroll
            for (int mi = 0; mi < 8; mi++)
                #pragma unroll
                for (int ni = 0; ni < 8; ni++)
                    acc[mi][ni] += ra[mi] * rb[ni];
        }
        __syncthreads();
    }

    const float bv = baff[0];
    float* dst = g_aff + (size_t)b * Nc * Nc;
    #pragma unroll
    for (int mi = 0; mi < 8; mi++) {
        int i = i0 + tm0 + mi;
        float4 o0 = make_float4(acc[mi][0]+bv, acc[mi][1]+bv, acc[mi][2]+bv, acc[mi][3]+bv);
        float4 o1 = make_float4(acc[mi][4]+bv, acc[mi][5]+bv, acc[mi][6]+bv, acc[mi][7]+bv);
        *(float4*)&dst[(size_t)i * Nc + j0 + tn0]     = o0;
        *(float4*)&dst[(size_t)i * Nc + j0 + tn0 + 4] = o1;
    }
}

// ---------------- row sum of exp(aff): r2 = 0.5 / rowsum ----------------
__global__ __launch_bounds__(256) void rowsum_kernel() {
    int warp = threadIdx.x >> 5, lane = threadIdx.x & 31;
    int row = blockIdx.x * 8 + warp;
    const float* p = g_aff + (size_t)row * Nc;
    float acc = 0.f;
    #pragma unroll
    for (int it = 0; it < 4; it++) {
        float4 v = *(const float4*)&p[it * 128 + lane * 4];
        acc += __expf(v.x) + __expf(v.y) + __expf(v.z) + __expf(v.w);
    }
    #pragma unroll
    for (int o = 16; o; o >>= 1) acc += __shfl_xor_sync(0xffffffffu, acc, o);
    if (lane == 0) g_r2[row] = 0.5f / acc;
}

// ---------------- column sum of exp(aff), partials over 8 i-chunks ----------------
__global__ __launch_bounds__(512) void colsum_kernel() {
    int chunk = blockIdx.x, b = blockIdx.y, j = threadIdx.x;
    const float* p = g_aff + ((size_t)b * Nc + chunk * 64) * Nc + j;
    float acc = 0.f;
    #pragma unroll 8
    for (int ii = 0; ii < 64; ii++) acc += __expf(p[(size_t)ii * Nc]);
    g_vpart[((size_t)chunk * Bc + b) * Nc + j] = acc;
}

__global__ __launch_bounds__(256) void colfin_kernel() {
    int idx = blockIdx.x * 256 + threadIdx.x;
    float s = 0.f;
    #pragma unroll
    for (int c = 0; c < NCHUNK; c++) s += g_vpart[(size_t)c * NROWS + idx];
    g_r1[idx] = 0.5f / s;
}

// ---------------- Kh = fp16( exp(aff) * (r1[b,j] + r2[b,i]) ) ----------------
__global__ __launch_bounds__(256) void kbuild_kernel() {
    int idx4 = blockIdx.x * 256 + threadIdx.x;   // float4 index
    int j4 = idx4 & 127;
    int rowIdx = idx4 >> 7;
    int b = rowIdx >> 9;
    float4 a4 = ((const float4*)g_aff)[idx4];
    float r2v = g_r2[rowIdx];
    float4 r1v = *(const float4*)&g_r1[b * Nc + j4 * 4];
    __half2 h0 = __floats2half2_rn(__expf(a4.x) * (r1v.x + r2v),
                                   __expf(a4.y) * (r1v.y + r2v));
    __half2 h1 = __floats2half2_rn(__expf(a4.z) * (r1v.z + r2v),
                                   __expf(a4.w) * (r1v.w + r2v));
    __half2* dst = (__half2*)g_Kh;
    dst[idx4 * 2]     = h0;
    dst[idx4 * 2 + 1] = h1;
}

// ---------------- v-partials init so that first v == 1 ----------------
__global__ __launch_bounds__(256) void vinit_kernel() {
    int idx = blockIdx.x * 256 + threadIdx.x;
    g_vpart[idx] = (idx < NROWS) ? 1.0f : 0.0f;
}

// ---------------- Sinkhorn row matvec (fp16 K): u = 1/(K v) ----------------
__global__ __launch_bounds__(512) void rowmv_kernel() {
    __shared__ float v_s[Nc];
    int rb = blockIdx.x, b = blockIdx.y;
    int tid = threadIdx.x;
    {
        float s = 0.f;
        #pragma unroll
        for (int c = 0; c < NCHUNK; c++) s += g_vpart[(size_t)c * NROWS + b * Nc + tid];
        v_s[tid] = 1.0f / s;
    }
    __syncthreads();
    int warp = tid >> 5, lane = tid & 31;
    int i0 = rb * 64 + warp * 4;
    #pragma unroll
    for (int rr = 0; rr < 4; rr++) {
        int i = i0 + rr;
        const uint4* kp4 = (const uint4*)(g_Kh + ((size_t)b * Nc + i) * Nc);  // 64 uint4/row
        float acc = 0.f;
        #pragma unroll
        for (int it = 0; it < 2; it++) {
            uint4 q = kp4[it * 32 + lane];                 // 8 halves
            int vb0 = (it * 32 + lane) * 8;
            float2 f0 = __half22float2(*(__half2*)&q.x);
            float2 f1 = __half22float2(*(__half2*)&q.y);
            float2 f2 = __half22float2(*(__half2*)&q.z);
            float2 f3 = __half22float2(*(__half2*)&q.w);
            float4 va = *(float4*)&v_s[vb0];
            float4 vb = *(float4*)&v_s[vb0 + 4];
            acc += f0.x*va.x + f0.y*va.y + f1.x*va.z + f1.y*va.w
                 + f2.x*vb.x + f2.y*vb.y + f3.x*vb.z + f3.y*vb.w;
        }
        #pragma unroll
        for (int o = 16; o; o >>= 1) acc += __shfl_xor_sync(0xffffffffu, acc, o);
        if (lane == 0) g_u[b * Nc + i] = 1.0f / acc;
    }
}

// ---------------- Sinkhorn col matvec partials (fp16 K): vpart[c] = K^T u ----------------
__global__ __launch_bounds__(512) void colmv_kernel() {
    __shared__ float u_s[64];
    int chunk = blockIdx.x, b = blockIdx.y;
    int j = threadIdx.x;
    if (j < 64) u_s[j] = g_u[b * Nc + chunk * 64 + j];
    __syncthreads();
    const __half* kp = g_Kh + ((size_t)b * Nc + chunk * 64) * Nc + j;
    float acc = 0.f;
    #pragma unroll 8
    for (int ii = 0; ii < 64; ii++) acc += __half2float(kp[(size_t)ii * Nc]) * u_s[ii];
    g_vpart[((size_t)chunk * Bc + b) * Nc + j] = acc;
}

// ---------------- final: out = u[i] * exp(aff)*(r1[j]+r2[i]) * v[j]  (fp32 path) ----------------
__global__ __launch_bounds__(512) void final_kernel(float* __restrict__ out) {
    __shared__ float u_s[64], r2_s[64];
    int rb = blockIdx.x, b = blockIdx.y;
    int tid = threadIdx.x;
    float s = 0.f;
    #pragma unroll
    for (int c = 0; c < NCHUNK; c++) s += g_vpart[(size_t)c * NROWS + b * Nc + tid];
    float vj = 1.0f / s;
    float r1j = g_r1[b * Nc + tid];
    if (tid < 64) {
        u_s[tid]  = g_u[b * Nc + rb * 64 + tid];
        r2_s[tid] = g_r2[b * Nc + rb * 64 + tid];
    }
    __syncthreads();
    #pragma unroll 4
    for (int ii = 0; ii < 64; ii++) {
        size_t off = ((size_t)b * Nc + rb * 64 + ii) * Nc + tid;
        out[off] = __expf(g_aff[off]) * (r1j + r2_s[ii]) * (u_s[ii] * vj);
    }
}

// ---------------- launch ----------------
extern "C" void kernel_launch(void* const* d_in, const int* in_sizes, int n_in,
                              void* d_out, int out_size) {
    const float* in_emb  = (const float*)d_in[0];
    const void*  maskp   = d_in[1];
    const float* out_emb = (const float*)d_in[2];
    const float* pad     = (const float*)d_in[3];
    const float* pos     = (const float*)d_in[4];
    const float* Wa      = (const float*)d_in[5];
    const float* Wb      = (const float*)d_in[6];
    const float* w_aff   = (const float*)d_in[7];
    const float* baff    = (const float*)d_in[8];

    detect_mask_kernel<<<1, 256>>>((const unsigned int*)maskp);
    prep_gemm_kernel<<<dim3(NROWS / 128, 1, 2), 256>>>(in_emb, maskp, out_emb, pad, pos, Wa, Wb, w_aff);
    aff_gemm_kernel<<<dim3(4, 4, Bc), 256>>>(baff);
    rowsum_kernel<<<NROWS / 8, 256>>>();
    colsum_kernel<<<dim3(NCHUNK, Bc), 512>>>();
    colfin_kernel<<<NROWS / 256, 256>>>();
    kbuild_kernel<<<(Bc * Nc * Nc / 4) / 256, 256>>>();
    vinit_kernel<<<(NCHUNK * NROWS) / 256, 256>>>();
    for (int t = 0; t < NITER; t++) {
        rowmv_kernel<<<dim3(8, Bc), 512>>>();
        colmv_kernel<<<dim3(NCHUNK, Bc), 512>>>();
    }
    final_kernel<<<dim3(8, Bc), 512>>>((float*)d_out);
}

// round 4
// speedup vs baseline: 1.7098x; 1.1139x over previous
#include <cuda_runtime.h>
#include <cuda_fp16.h>
#include <cstdint>

#define Bc 64
#define Nc 512
#define Dc 256
#define Ec 128
#define NITER 20
#define NROWS (Bc*Nc)          // 32768
#define NCHUNK 8

// ---------------- scratch ----------------
__device__ float  g_a[Bc*Nc*Ec];
__device__ float  g_b[Bc*Nc*Ec];
__device__ float  g_aff[Bc*Nc*Nc];          // 67 MB fp32 affinity
__device__ __half g_Kh[Bc*Nc*Nc];           // 33.5 MB fp16 K (L2-resident)
__device__ float  g_r1[NROWS];
__device__ float  g_r2[NROWS];
__device__ float  g_u[NROWS];
__device__ float  g_vpart[2][NCHUNK*NROWS]; // ping-pong column partials
__device__ float  g_rspart[4*NROWS];        // rowsum(exp) partials by j-block
__device__ float  g_cspart[4*NROWS];        // colsum(exp) partials by i-block
__device__ int    g_mask_mode;

// ---------------- f32x2 helpers ----------------
__device__ __forceinline__ uint64_t pk2(float x, float y) {
    uint64_t r; asm("mov.b64 %0, {%1, %2};" : "=l"(r) : "f"(x), "f"(y)); return r;
}
__device__ __forceinline__ void upk2(uint64_t v, float& x, float& y) {
    asm("mov.b64 {%0, %1}, %2;" : "=f"(x), "=f"(y) : "l"(v));
}
__device__ __forceinline__ void ffma2(uint64_t& d, uint64_t a, uint64_t b) {
    asm("fma.rn.f32x2 %0, %1, %2, %0;" : "+l"(d) : "l"(a), "l"(b));
}

// ---------------- mask dtype detection ----------------
__global__ void detect_mask_kernel(const unsigned int* __restrict__ m) {
    __shared__ int bad_i32, bad_f32;
    if (threadIdx.x == 0) { bad_i32 = 0; bad_f32 = 0; }
    __syncthreads();
    for (int i = threadIdx.x; i < 8192; i += blockDim.x) {
        unsigned int w = m[i];
        if (w != 0u && w != 1u)          atomicOr(&bad_i32, 1);
        if (w != 0u && w != 0x3F800000u) atomicOr(&bad_f32, 1);
    }
    __syncthreads();
    if (threadIdx.x == 0) g_mask_mode = bad_i32 ? (bad_f32 ? 2 : 1) : 0;
}

__device__ __forceinline__ bool read_mask(const void* mp, int row) {
    int mode = g_mask_mode;
    if (mode == 2) return ((const unsigned char*)mp)[row] != 0;
    if (mode == 1) return ((const float*)mp)[row] != 0.0f;
    return ((const int*)mp)[row] != 0;
}

// ---------------- prep GEMM (f32x2) ----------------
#define PBK 16
#define ASTRIDE 132

__global__ __launch_bounds__(256, 2) void prep_gemm_kernel(
    const float* __restrict__ in_emb, const void* __restrict__ maskp,
    const float* __restrict__ out_emb, const float* __restrict__ pad,
    const float* __restrict__ pos, const float* __restrict__ Wa,
    const float* __restrict__ Wb, const float* __restrict__ w_aff)
{
    __shared__ float As[PBK][ASTRIDE];
    __shared__ float Bs[PBK][128];
    const int zb = blockIdx.z;
    const int row0 = blockIdx.x * 128;
    const int tid = threadIdx.x;
    const float* W = zb ? Wb : Wa;
    uint64_t acc2[4][8] = {};   // [mi_pair][ni], lanes = (2mp, 2mp+1)
    const int tm0 = (tid / 16) * 8;
    const int tn0 = (tid % 16) * 8;
    const int lm = tid >> 2, kg = tid & 3;

    for (int k0 = 0; k0 < Dc; k0 += PBK) {
        #pragma unroll
        for (int p = 0; p < 2; p++) {
            int m = lm + p * 64;
            int row = row0 + m;
            int n = row & (Nc - 1);
            int kk = k0 + kg * 4;
            float4 v;
            if (zb == 0) {
                float4 a4 = *(const float4*)&out_emb[(size_t)row * Dc + kk];
                float4 p4 = *(const float4*)&pos[n * Dc + kk];
                v = make_float4(a4.x + p4.x, a4.y + p4.y, a4.z + p4.z, a4.w + p4.w);
            } else {
                if (read_mask(maskp, row)) v = *(const float4*)&pad[kk];
                else                       v = *(const float4*)&in_emb[(size_t)row * Dc + kk];
            }
            As[kg*4+0][m] = v.x; As[kg*4+1][m] = v.y;
            As[kg*4+2][m] = v.z; As[kg*4+3][m] = v.w;
        }
        {
            int r = tid >> 5;
            int c4 = (tid & 31) * 4;
            #pragma unroll
            for (int p = 0; p < 2; p++) {
                int kk = r + p * 8;
                *(float4*)&Bs[kk][c4] = *(const float4*)&W[(k0 + kk) * Ec + c4];
            }
        }
        __syncthreads();
        #pragma unroll
        for (int k = 0; k < PBK; k++) {
            float ra[8], rb[8];
            *(float4*)&ra[0] = *(float4*)&As[k][tm0];
            *(float4*)&ra[4] = *(float4*)&As[k][tm0 + 4];
            *(float4*)&rb[0] = *(float4*)&Bs[k][tn0];
            *(float4*)&rb[4] = *(float4*)&Bs[k][tn0 + 4];
            uint64_t aP[4], bP[8];
            #pragma unroll
            for (int mp = 0; mp < 4; mp++) aP[mp] = pk2(ra[2*mp], ra[2*mp+1]);
            #pragma unroll
            for (int ni = 0; ni < 8; ni++) bP[ni] = pk2(rb[ni], rb[ni]);
            #pragma unroll
            for (int mp = 0; mp < 4; mp++)
                #pragma unroll
                for (int ni = 0; ni < 8; ni++)
                    ffma2(acc2[mp][ni], aP[mp], bP[ni]);
        }
        __syncthreads();
    }

    float acc[8][8];
    #pragma unroll
    for (int mp = 0; mp < 4; mp++)
        #pragma unroll
        for (int ni = 0; ni < 8; ni++)
            upk2(acc2[mp][ni], acc[2*mp][ni], acc[2*mp+1][ni]);

    float* dst = zb ? g_b : g_a;
    float wv[8];
    if (zb == 0) {
        *(float4*)&wv[0] = *(const float4*)&w_aff[tn0];
        *(float4*)&wv[4] = *(const float4*)&w_aff[tn0 + 4];
    } else {
        #pragma unroll
        for (int i = 0; i < 8; i++) wv[i] = 1.0f;
    }
    #pragma unroll
    for (int mi = 0; mi < 8; mi++) {
        int row = row0 + tm0 + mi;
        float4 o0 = make_float4(acc[mi][0]*wv[0], acc[mi][1]*wv[1], acc[mi][2]*wv[2], acc[mi][3]*wv[3]);
        float4 o1 = make_float4(acc[mi][4]*wv[4], acc[mi][5]*wv[5], acc[mi][6]*wv[6], acc[mi][7]*wv[7]);
        *(float4*)&dst[(size_t)row * Ec + tn0]     = o0;
        *(float4*)&dst[(size_t)row * Ec + tn0 + 4] = o1;
    }
}

// ---------------- aff GEMM (f32x2) + fused exp row/col sum partials ----------------
__global__ __launch_bounds__(256, 2) void aff_gemm_kernel(const float* __restrict__ baff)
{
    __shared__ float As[PBK][ASTRIDE];
    __shared__ float Bs[PBK][ASTRIDE];
    __shared__ float s_row[16][128];
    __shared__ float s_col[16][128];
    const int b = blockIdx.z;
    const int i0 = blockIdx.x * 128, j0 = blockIdx.y * 128;
    const int tid = threadIdx.x;
    uint64_t acc2[4][8] = {};
    const int tm0 = (tid / 16) * 8, tn0 = (tid % 16) * 8;
    const int lm = tid >> 2, kg = tid & 3;
    const float* Ab = g_a + (size_t)b * Nc * Ec;
    const float* Bb = g_b + (size_t)b * Nc * Ec;

    for (int k0 = 0; k0 < Ec; k0 += PBK) {
        #pragma unroll
        for (int p = 0; p < 2; p++) {
            int m = lm + p * 64;
            float4 va = *(const float4*)&Ab[(size_t)(i0 + m) * Ec + k0 + kg * 4];
            As[kg*4+0][m] = va.x; As[kg*4+1][m] = va.y;
            As[kg*4+2][m] = va.z; As[kg*4+3][m] = va.w;
            float4 vb = *(const float4*)&Bb[(size_t)(j0 + m) * Ec + k0 + kg * 4];
            Bs[kg*4+0][m] = vb.x; Bs[kg*4+1][m] = vb.y;
            Bs[kg*4+2][m] = vb.z; Bs[kg*4+3][m] = vb.w;
        }
        __syncthreads();
        #pragma unroll
        for (int k = 0; k < PBK; k++) {
            float ra[8], rb[8];
            *(float4*)&ra[0] = *(float4*)&As[k][tm0];
            *(float4*)&ra[4] = *(float4*)&As[k][tm0 + 4];
            *(float4*)&rb[0] = *(float4*)&Bs[k][tn0];
            *(float4*)&rb[4] = *(float4*)&Bs[k][tn0 + 4];
            uint64_t aP[4], bP[8];
            #pragma unroll
            for (int mp = 0; mp < 4; mp++) aP[mp] = pk2(ra[2*mp], ra[2*mp+1]);
            #pragma unroll
            for (int ni = 0; ni < 8; ni++) bP[ni] = pk2(rb[ni], rb[ni]);
            #pragma unroll
            for (int mp = 0; mp < 4; mp++)
                #pragma unroll
                for (int ni = 0; ni < 8; ni++)
                    ffma2(acc2[mp][ni], aP[mp], bP[ni]);
        }
        __syncthreads();
    }

    float acc[8][8];
    #pragma unroll
    for (int mp = 0; mp < 4; mp++)
        #pragma unroll
        for (int ni = 0; ni < 8; ni++)
            upk2(acc2[mp][ni], acc[2*mp][ni], acc[2*mp+1][ni]);

    const float bv = baff[0];
    float* dst = g_aff + (size_t)b * Nc * Nc;
    float rsum[8], csum[8];
    #pragma unroll
    for (int q = 0; q < 8; q++) { rsum[q] = 0.f; csum[q] = 0.f; }
    #pragma unroll
    for (int mi = 0; mi < 8; mi++) {
        int i = i0 + tm0 + mi;
        float t[8];
        #pragma unroll
        for (int ni = 0; ni < 8; ni++) t[ni] = acc[mi][ni] + bv;
        *(float4*)&dst[(size_t)i * Nc + j0 + tn0]     = *(float4*)&t[0];
        *(float4*)&dst[(size_t)i * Nc + j0 + tn0 + 4] = *(float4*)&t[4];
        #pragma unroll
        for (int ni = 0; ni < 8; ni++) {
            float ev = __expf(t[ni]);
            rsum[mi] += ev;
            csum[ni] += ev;
        }
    }
    {
        int tr = tid & 15;      // which j-slice this thread's rows pair with
        int tc = tid >> 4;      // which i-slice this thread's cols pair with
        #pragma unroll
        for (int mi = 0; mi < 8; mi++) s_row[tr][tm0 + mi] = rsum[mi];
        #pragma unroll
        for (int ni = 0; ni < 8; ni++) s_col[tc][tn0 + ni] = csum[ni];
    }
    __syncthreads();
    if (tid < 128) {
        float s = 0.f;
        #pragma unroll
        for (int p = 0; p < 16; p++) s += s_row[p][tid];
        g_rspart[(size_t)blockIdx.y * NROWS + b * Nc + i0 + tid] = s;
    } else {
        int t = tid - 128;
        float s = 0.f;
        #pragma unroll
        for (int p = 0; p < 16; p++) s += s_col[p][t];
        g_cspart[(size_t)blockIdx.x * NROWS + b * Nc + j0 + t] = s;
    }
}

// ---------------- r1/r2 finalize ----------------
__global__ __launch_bounds__(256) void rfin_kernel() {
    int idx = blockIdx.x * 256 + threadIdx.x;
    float rs = 0.f, cs = 0.f;
    #pragma unroll
    for (int p = 0; p < 4; p++) {
        rs += g_rspart[(size_t)p * NROWS + idx];
        cs += g_cspart[(size_t)p * NROWS + idx];
    }
    g_r2[idx] = 0.5f / rs;
    g_r1[idx] = 0.5f / cs;
}

// ---------------- Kh = fp16( exp(aff) * (r1[b,j] + r2[b,i]) ) ----------------
__global__ __launch_bounds__(256) void kbuild_kernel() {
    int idx4 = blockIdx.x * 256 + threadIdx.x;
    int j4 = idx4 & 127;
    int rowIdx = idx4 >> 7;
    int b = rowIdx >> 9;
    float4 a4 = ((const float4*)g_aff)[idx4];
    float r2v = g_r2[rowIdx];
    float4 r1v = *(const float4*)&g_r1[b * Nc + j4 * 4];
    __half2 h0 = __floats2half2_rn(__expf(a4.x) * (r1v.x + r2v),
                                   __expf(a4.y) * (r1v.y + r2v));
    __half2 h1 = __floats2half2_rn(__expf(a4.z) * (r1v.z + r2v),
                                   __expf(a4.w) * (r1v.w + r2v));
    __half2* dst = (__half2*)g_Kh;
    dst[idx4 * 2]     = h0;
    dst[idx4 * 2 + 1] = h1;
}

// ---------------- vpart init (buffer 0 -> v = 1) ----------------
__global__ __launch_bounds__(256) void vinit_kernel() {
    int idx = blockIdx.x * 256 + threadIdx.x;
    g_vpart[0][idx] = (idx < NROWS) ? 1.0f : 0.0f;
}

// ---------------- fused Sinkhorn iteration ----------------
// block (chunk c, batch b): stage K tile (64x512 fp16) in smem once;
// compute u for the 64 rows, then column partials weighted by u.
#define SMEM_SINK (65536 + 2048 + 256 + 16384)

__global__ __launch_bounds__(512) void sink_iter_kernel(int pr) {
    extern __shared__ char sm[];
    __half* Ks  = (__half*)sm;                    // [64][512]
    float* v_s  = (float*)(sm + 65536);           // [512]
    float* u_s  = v_s + 512;                      // [64]
    float* pbuf = u_s + 64;                       // [8][512]
    const int c = blockIdx.x, b = blockIdx.y, tid = threadIdx.x;

    {   // reconstruct v from previous iteration's partials (buffer pr)
        float s = 0.f;
        #pragma unroll
        for (int cc = 0; cc < NCHUNK; cc++)
            s += g_vpart[pr][(size_t)cc * NROWS + b * Nc + tid];
        v_s[tid] = 1.0f / s;
    }
    {   // stage tile
        const uint4* gk = (const uint4*)(g_Kh + ((size_t)b * Nc + c * 64) * Nc);
        uint4* sk = (uint4*)Ks;
        #pragma unroll
        for (int it = 0; it < 8; it++) sk[tid + it * 512] = gk[tid + it * 512];
    }
    __syncthreads();

    const int warp = tid >> 5, lane = tid & 31;
    // hoist this lane's v slices into registers (reused across 4 rows)
    float vv[16];
    *(float4*)&vv[0]  = *(const float4*)&v_s[lane * 8];
    *(float4*)&vv[4]  = *(const float4*)&v_s[lane * 8 + 4];
    *(float4*)&vv[8]  = *(const float4*)&v_s[(lane + 32) * 8];
    *(float4*)&vv[12] = *(const float4*)&v_s[(lane + 32) * 8 + 4];

    #pragma unroll
    for (int rr = 0; rr < 4; rr++) {
        int i = warp * 4 + rr;
        const uint4* row = (const uint4*)(Ks + i * Nc);
        float acc = 0.f;
        #pragma unroll
        for (int it = 0; it < 2; it++) {
            uint4 q = row[lane + it * 32];
            const float* vr = &vv[it * 8];
            float2 f0 = __half22float2(*(__half2*)&q.x);
            float2 f1 = __half22float2(*(__half2*)&q.y);
            float2 f2 = __half22float2(*(__half2*)&q.z);
            float2 f3 = __half22float2(*(__half2*)&q.w);
            acc += f0.x*vr[0] + f0.y*vr[1] + f1.x*vr[2] + f1.y*vr[3]
                 + f2.x*vr[4] + f2.y*vr[5] + f3.x*vr[6] + f3.y*vr[7];
        }
        #pragma unroll
        for (int o = 16; o; o >>= 1) acc += __shfl_xor_sync(0xffffffffu, acc, o);
        if (lane == 0) {
            float u = 1.0f / acc;
            u_s[i] = u;
            g_u[b * Nc + c * 64 + i] = u;
        }
    }
    __syncthreads();

    // column partials: 8 i-groups x 64 col-groups of 8
    const int ig = tid >> 6, jg = tid & 63;
    float a8[8] = {};
    #pragma unroll
    for (int ii = 0; ii < 8; ii++) {
        int i = ig * 8 + ii;
        uint4 q = ((const uint4*)(Ks + i * Nc))[jg];
        float ui = u_s[i];
        float2 f0 = __half22float2(*(__half2*)&q.x);
        float2 f1 = __half22float2(*(__half2*)&q.y);
        float2 f2 = __half22float2(*(__half2*)&q.z);
        float2 f3 = __half22float2(*(__half2*)&q.w);
        a8[0] += f0.x * ui; a8[1] += f0.y * ui;
        a8[2] += f1.x * ui; a8[3] += f1.y * ui;
        a8[4] += f2.x * ui; a8[5] += f2.y * ui;
        a8[6] += f3.x * ui; a8[7] += f3.y * ui;
    }
    *(float4*)&pbuf[ig * 512 + jg * 8]     = make_float4(a8[0], a8[1], a8[2], a8[3]);
    *(float4*)&pbuf[ig * 512 + jg * 8 + 4] = make_float4(a8[4], a8[5], a8[6], a8[7]);
    __syncthreads();
    {
        float s = 0.f;
        #pragma unroll
        for (int ii = 0; ii < 8; ii++) s += pbuf[ii * 512 + tid];
        g_vpart[pr ^ 1][(size_t)c * NROWS + b * Nc + tid] = s;
    }
}

// ---------------- final: out = u[i] * Kh * v[j] ----------------
__global__ __launch_bounds__(512) void final_kernel(float* __restrict__ out, int pr) {
    __shared__ float u_s[64];
    __shared__ float v_sh[512];
    const int c = blockIdx.x, b = blockIdx.y, tid = threadIdx.x;
    {
        float s = 0.f;
        #pragma unroll
        for (int cc = 0; cc < NCHUNK; cc++)
            s += g_vpart[pr][(size_t)cc * NROWS + b * Nc + tid];
        v_sh[tid] = 1.0f / s;
    }
    if (tid < 64) u_s[tid] = g_u[b * Nc + c * 64 + tid];
    __syncthreads();
    const uint4* kp = (const uint4*)(g_Kh + ((size_t)b * Nc + c * 64) * Nc);
    #pragma unroll
    for (int it = 0; it < 8; it++) {
        int idx = tid + it * 512;
        int i = idx >> 6, j4 = idx & 63;
        uint4 q = kp[idx];
        float ui = u_s[i];
        const float* vp = &v_sh[j4 * 8];
        float2 f0 = __half22float2(*(__half2*)&q.x);
        float2 f1 = __half22float2(*(__half2*)&q.y);
        float2 f2 = __half22float2(*(__half2*)&q.z);
        float2 f3 = __half22float2(*(__half2*)&q.w);
        float4 o0 = make_float4(f0.x*ui*vp[0], f0.y*ui*vp[1], f1.x*ui*vp[2], f1.y*ui*vp[3]);
        float4 o1 = make_float4(f2.x*ui*vp[4], f2.y*ui*vp[5], f3.x*ui*vp[6], f3.y*ui*vp[7]);
        size_t off = ((size_t)b * Nc + c * 64 + i) * Nc + j4 * 8;
        *(float4*)&out[off]     = o0;
        *(float4*)&out[off + 4] = o1;
    }
}

// ---------------- launch ----------------
extern "C" void kernel_launch(void* const* d_in, const int* in_sizes, int n_in,
                              void* d_out, int out_size) {
    const float* in_emb  = (const float*)d_in[0];
    const void*  maskp   = d_in[1];
    const float* out_emb = (const float*)d_in[2];
    const float* pad     = (const float*)d_in[3];
    const float* pos     = (const float*)d_in[4];
    const float* Wa      = (const float*)d_in[5];
    const float* Wb      = (const float*)d_in[6];
    const float* w_aff   = (const float*)d_in[7];
    const float* baff    = (const float*)d_in[8];

    cudaFuncSetAttribute(sink_iter_kernel,
                         cudaFuncAttributeMaxDynamicSharedMemorySize, SMEM_SINK);

    detect_mask_kernel<<<1, 256>>>((const unsigned int*)maskp);
    vinit_kernel<<<(NCHUNK * NROWS) / 256, 256>>>();
    prep_gemm_kernel<<<dim3(NROWS / 128, 1, 2), 256>>>(in_emb, maskp, out_emb, pad, pos, Wa, Wb, w_aff);
    aff_gemm_kernel<<<dim3(4, 4, Bc), 256>>>(baff);
    rfin_kernel<<<NROWS / 256, 256>>>();
    kbuild_kernel<<<(Bc * Nc * Nc / 4) / 256, 256>>>();
    for (int t = 0; t < NITER; t++) {
        sink_iter_kernel<<<dim3(NCHUNK, Bc), 512, SMEM_SINK>>>(t & 1);
    }
    final_kernel<<<dim3(NCHUNK, Bc), 512>>>((float*)d_out, NITER & 1);
}